// round 16
// baseline (speedup 1.0000x reference)
#include <cuda_runtime.h>
#include <cuda_bf16.h>
#include <math.h>
#include <stdint.h>

// ---------------- problem constants ----------------
#define BATCH 128
#define CH    3
#define HIM   224
#define PGRID 14
#define NP    196
#define PATCH 16
#define IN_D  768
#define DMODEL 256
#define NHEAD 8
#define DH    32
#define NLAYER 4
#define SEQ   197
#define OUTC  1000
#define OUTP  1024
#define HKDIM 768            // head GEMM K = 3*DMODEL
#define LNEPS 1e-5f

typedef __nv_bfloat16 bf16;

// ---------------- scratch (device globals) ----------------
__device__ bf16  g_patches_b[BATCH * NP * IN_D];
__device__ float g_X [BATCH * SEQ * DMODEL];
__device__ bf16  g_x1b[BATCH * SEQ * DMODEL];
__device__ bf16  g_qb [BATCH * SEQ * DMODEL];             // [n,h,s,e] (pre-scaled by scale*log2e)
__device__ bf16  g_kb [BATCH * SEQ * DMODEL];
__device__ bf16  g_vb [BATCH * SEQ * DMODEL];
__device__ bf16  g_ob [BATCH * SEQ * DMODEL];             // [n,s,d]
__device__ bf16  g_h1b[BATCH * SEQ * 4 * DMODEL];
__device__ float g_pe[SEQ * DMODEL];
__device__ bf16  g_wmapb [DMODEL * IN_D];
__device__ bf16  g_wlastb[NLAYER * DMODEL * DMODEL];
__device__ bf16  g_wmlp1b[NLAYER * 4 * DMODEL * DMODEL];
__device__ bf16  g_wmlp2b[NLAYER * 4 * DMODEL * DMODEL];
__device__ bf16  g_wout_cat[OUTP * HKDIM];                // [whi | wlo | whi]
__device__ float g_bout_pad[OUTP];
__device__ bf16  g_cls_cat[BATCH * HKDIM];                // [chi | chi | clo]
__device__ float g_logits[BATCH * OUTP];

__device__ __forceinline__ float ex2f(float x)
{
    float r;
    asm("ex2.approx.f32 %0, %1;" : "=f"(r) : "f"(x));
    return r;
}

// ---------------- fp32 -> bf16 convert, all weights in one launch ----------
__device__ __forceinline__ void cvt4(const float* __restrict__ s, bf16* __restrict__ d, int i)
{
    float4 v = *(const float4*)(s + i);
    __nv_bfloat162 p0 = __floats2bfloat162_rn(v.x, v.y);
    __nv_bfloat162 p1 = __floats2bfloat162_rn(v.z, v.w);
    uint2 o;
    o.x = *reinterpret_cast<uint32_t*>(&p0);
    o.y = *reinterpret_cast<uint32_t*>(&p1);
    *reinterpret_cast<uint2*>(d + i) = o;
}

__global__ void cvt_all_kernel(const float* __restrict__ s0, bf16* __restrict__ d0, int n0,
                               const float* __restrict__ s1, bf16* __restrict__ d1, int n1,
                               const float* __restrict__ s2, bf16* __restrict__ d2, int n2,
                               const float* __restrict__ s3, bf16* __restrict__ d3, int n3)
{
    int i = (blockIdx.x * 256 + threadIdx.x) * 4;
    if (i < n0) { cvt4(s0, d0, i); return; }
    i -= n0;
    if (i < n1) { cvt4(s1, d1, i); return; }
    i -= n1;
    if (i < n2) { cvt4(s2, d2, i); return; }
    i -= n2;
    if (i < n3) { cvt4(s3, d3, i); return; }
}

// ---------------- head weight: pad + hi/lo split -> concat [whi|wlo|whi] ----
__global__ void cvt_head_kernel(const float* __restrict__ w_out, const float* __restrict__ b_out,
                                bf16* __restrict__ wcat, float* __restrict__ bpad)
{
    int tid = blockIdx.x * 256 + threadIdx.x;
    int i = tid * 4;
    if (i < OUTP * DMODEL) {
        int row = i / DMODEL, col = i % DMODEL;
        bf16* wr = wcat + (size_t)row * HKDIM;
        if (row < OUTC) {
            float4 v = *(const float4*)(w_out + i);
            bf16 h0 = __float2bfloat16(v.x), h1 = __float2bfloat16(v.y);
            bf16 h2 = __float2bfloat16(v.z), h3 = __float2bfloat16(v.w);
            bf16 l0 = __float2bfloat16(v.x - __bfloat162float(h0));
            bf16 l1 = __float2bfloat16(v.y - __bfloat162float(h1));
            bf16 l2 = __float2bfloat16(v.z - __bfloat162float(h2));
            bf16 l3 = __float2bfloat16(v.w - __bfloat162float(h3));
            wr[col]     = h0; wr[col + 1] = h1; wr[col + 2] = h2; wr[col + 3] = h3;
            wr[DMODEL + col]     = l0; wr[DMODEL + col + 1] = l1;
            wr[DMODEL + col + 2] = l2; wr[DMODEL + col + 3] = l3;
            wr[2 * DMODEL + col]     = h0; wr[2 * DMODEL + col + 1] = h1;
            wr[2 * DMODEL + col + 2] = h2; wr[2 * DMODEL + col + 3] = h3;
        } else {
            uint2 z = {0u, 0u};
            *reinterpret_cast<uint2*>(wr + col) = z;
            *reinterpret_cast<uint2*>(wr + DMODEL + col) = z;
            *reinterpret_cast<uint2*>(wr + 2 * DMODEL + col) = z;
        }
    }
    if (tid < OUTP) bpad[tid] = (tid < OUTC) ? b_out[tid] : 0.f;
}

// ---------------- cls row extraction -> concat [chi|chi|clo] ----------------
__global__ void cls_extract_kernel(const float* __restrict__ X, bf16* __restrict__ ccat)
{
    int i = (blockIdx.x * 256 + threadIdx.x) * 4;
    if (i >= BATCH * DMODEL) return;
    int n = i / DMODEL, d = i % DMODEL;
    float4 v = *(const float4*)(X + (size_t)n * SEQ * DMODEL + d);
    bf16 h0 = __float2bfloat16(v.x), h1 = __float2bfloat16(v.y);
    bf16 h2 = __float2bfloat16(v.z), h3 = __float2bfloat16(v.w);
    bf16 l0 = __float2bfloat16(v.x - __bfloat162float(h0));
    bf16 l1 = __float2bfloat16(v.y - __bfloat162float(h1));
    bf16 l2 = __float2bfloat16(v.z - __bfloat162float(h2));
    bf16 l3 = __float2bfloat16(v.w - __bfloat162float(h3));
    bf16* cr = ccat + (size_t)n * HKDIM;
    cr[d]     = h0; cr[d + 1] = h1; cr[d + 2] = h2; cr[d + 3] = h3;
    cr[DMODEL + d]     = h0; cr[DMODEL + d + 1] = h1;
    cr[DMODEL + d + 2] = h2; cr[DMODEL + d + 3] = h3;
    cr[2 * DMODEL + d]     = l0; cr[2 * DMODEL + d + 1] = l1;
    cr[2 * DMODEL + d + 2] = l2; cr[2 * DMODEL + d + 3] = l3;
}

// ---------------- patch extraction (float4 gather, writes bf16) ------------
__global__ void patch_kernel(const float* __restrict__ img, bf16* __restrict__ out)
{
    int tid = blockIdx.x * 256 + threadIdx.x;
    int idx = tid * 4;
    if (idx >= BATCH * NP * IN_D) return;
    int i = idx % IN_D;
    int p = (idx / IN_D) % NP;
    int n = idx / (IN_D * NP);
    int c   = i >> 8;
    int r   = (i >> 4) & 15;
    int col = i & 15;
    int py = p / PGRID, px = p % PGRID;
    float4 v = *(const float4*)(img + (((size_t)n * CH + c) * HIM + py * PATCH + r) * HIM
                                    + px * PATCH + col);
    __nv_bfloat162 p0 = __floats2bfloat162_rn(v.x, v.y);
    __nv_bfloat162 p1 = __floats2bfloat162_rn(v.z, v.w);
    uint2 o;
    o.x = *reinterpret_cast<uint32_t*>(&p0);
    o.y = *reinterpret_cast<uint32_t*>(&p1);
    *reinterpret_cast<uint2*>(out + idx) = o;
}

// ---------------- positional encoding (fp32) ----------------
__global__ void pe_kernel(float* __restrict__ pe)
{
    int i = blockIdx.x * 256 + threadIdx.x;
    if (i >= SEQ * DMODEL) return;
    int s = i / DMODEL, d = i % DMODEL;
    float expo = (float)(2 * (d / 2)) * (1.0f / DMODEL);
    float ang  = (float)s * powf(10000.0f, -expo);
    pe[i] = (d & 1) ? cosf(ang) : sinf(ang);
}

// ---------------- cls rows: X[n][0][:] = cls + pe[0] ------------------------
__global__ void cls_kernel(const float* __restrict__ cls,
                           const float* __restrict__ pe,
                           float* __restrict__ X)
{
    int i = blockIdx.x * 256 + threadIdx.x;
    if (i >= BATCH * DMODEL) return;
    int d = i % DMODEL;
    int n = i / DMODEL;
    X[(size_t)n * SEQ * DMODEL + d] = cls[d] + pe[d];
}

// ---------------- bf16 MMA / ldmatrix helpers -------------------------------
__device__ __forceinline__ void mma_bf16(float* c, const uint32_t* a, const uint32_t* b)
{
    asm volatile(
        "mma.sync.aligned.m16n8k16.row.col.f32.bf16.bf16.f32 "
        "{%0,%1,%2,%3}, {%4,%5,%6,%7}, {%8,%9}, {%0,%1,%2,%3};"
        : "+f"(c[0]), "+f"(c[1]), "+f"(c[2]), "+f"(c[3])
        : "r"(a[0]), "r"(a[1]), "r"(a[2]), "r"(a[3]), "r"(b[0]), "r"(b[1]));
}

#define LDSM4(r0, r1, r2, r3, addr) \
    asm volatile("ldmatrix.sync.aligned.m8n8.x4.shared.b16 {%0,%1,%2,%3}, [%4];" \
                 : "=r"(r0), "=r"(r1), "=r"(r2), "=r"(r3) : "r"(addr))

#define CP16(dst, src) asm volatile("cp.async.cg.shared.global [%0], [%1], 16;\n" :: "r"(dst), "l"(src))
#define CP_COMMIT()    asm volatile("cp.async.commit_group;\n" ::)
#define CP_WAIT1()     asm volatile("cp.async.wait_group 1;\n" ::)
#define CP_WAIT0()     asm volatile("cp.async.wait_group 0;\n" ::)

// ---------------- bf16 tensor-core GEMM, 128x128 tile (frozen config) -------
#define STR 36
#define ABUF (128 * STR)
#define GEMM_SMEM (4 * ABUF * 4)

template<int ACT, bool HASRES, bool OUTBF, bool ADDPE>
__global__ void __launch_bounds__(256) gemm_bf(const bf16* __restrict__ A,
                                               const bf16* __restrict__ W,
                                               const float* __restrict__ bias,
                                               const float* __restrict__ res,
                                               const float* __restrict__ pe,
                                               void* __restrict__ Cout,
                                               int M, int N, int K)
{
    extern __shared__ uint32_t sm_[];
    const uint32_t smem_byte = (uint32_t)__cvta_generic_to_shared(sm_);

    const int t    = threadIdx.x;
    const int warp = t >> 5, lane = t & 31;
    const int g    = lane >> 2, q4 = lane & 3;
    const int warp_m = (warp >> 1) * 32;
    const int warp_n = (warp & 1) * 64;
    const int row0 = blockIdx.y * 128, col0 = blockIdx.x * 128;

    float acc[2][8][4];
#pragma unroll
    for (int mi = 0; mi < 2; mi++)
#pragma unroll
        for (int ni = 0; ni < 8; ni++)
#pragma unroll
            for (int e = 0; e < 4; e++) acc[mi][ni][e] = 0.f;

    auto stage = [&](int k0, int buf) {
        uint32_t abase = smem_byte + buf * (ABUF * 4);
        uint32_t bbase = smem_byte + (2 + buf) * (ABUF * 4);
#pragma unroll
        for (int i = 0; i < 4; i++) {
            int c = t + i * 256;
            int r = c >> 3, co = c & 7;
            CP16(abase + (r * STR + co * 4) * 4, A + (size_t)(row0 + r) * K + k0 + co * 8);
            CP16(bbase + (r * STR + co * 4) * 4, W + (size_t)(col0 + r) * K + k0 + co * 8);
        }
        CP_COMMIT();
    };

    uint32_t a_addr[2][2], b_addr[2][4];
    {
        int ar = warp_m + (lane & 15);
        int ab = (lane >> 4) * 16;
        int br = warp_n + ((lane >> 4) & 1) * 8 + (lane & 7);
        int bb = ((lane >> 3) & 1) * 16;
#pragma unroll
        for (int buf = 0; buf < 2; buf++) {
            uint32_t abase = smem_byte + buf * (ABUF * 4);
            uint32_t bbase = smem_byte + (2 + buf) * (ABUF * 4);
#pragma unroll
            for (int mi = 0; mi < 2; mi++)
                a_addr[buf][mi] = abase + (ar + mi * 16) * (STR * 4) + ab;
#pragma unroll
            for (int nj = 0; nj < 4; nj++)
                b_addr[buf][nj] = bbase + (br + nj * 16) * (STR * 4) + bb;
        }
    }

    const int KT = K >> 6;
    stage(0, 0);

    for (int kt = 0; kt < KT; kt++) {
        const int cur = kt & 1;
        if (kt + 1 < KT) { stage((kt + 1) << 6, cur ^ 1); CP_WAIT1(); }
        else             { CP_WAIT0(); }
        __syncthreads();

#pragma unroll
        for (int ks = 0; ks < 4; ks++) {
            const uint32_t kb = ks * 32;
            uint32_t af[2][4];
            LDSM4(af[0][0], af[0][1], af[0][2], af[0][3], a_addr[cur][0] + kb);
            LDSM4(af[1][0], af[1][1], af[1][2], af[1][3], a_addr[cur][1] + kb);
            uint32_t bf_[8][2];
#pragma unroll
            for (int nj = 0; nj < 4; nj++)
                LDSM4(bf_[2 * nj][0], bf_[2 * nj][1], bf_[2 * nj + 1][0], bf_[2 * nj + 1][1],
                      b_addr[cur][nj] + kb);
#pragma unroll
            for (int mi = 0; mi < 2; mi++)
#pragma unroll
                for (int ni = 0; ni < 8; ni++)
                    mma_bf16(acc[mi][ni], af[mi], bf_[ni]);
        }
        __syncthreads();
    }

#pragma unroll
    for (int mi = 0; mi < 2; mi++) {
        int ra = row0 + warp_m + mi * 16 + g;
        int rb = ra + 8;
        size_t orow_a, orow_b;
        if (ADDPE) {
            orow_a = (size_t)(ra / NP) * SEQ + (ra % NP) + 1;
            orow_b = (size_t)(rb / NP) * SEQ + (rb % NP) + 1;
        } else {
            orow_a = ra; orow_b = rb;
        }
        int pes_a = ADDPE ? ((ra % NP) + 1) : 0;
        int pes_b = ADDPE ? ((rb % NP) + 1) : 0;
#pragma unroll
        for (int ni = 0; ni < 8; ni++) {
            int col = col0 + warp_n + ni * 8 + q4 * 2;
            float b0 = bias[col], b1 = bias[col + 1];
            float v00 = acc[mi][ni][0] + b0, v01 = acc[mi][ni][1] + b1;
            float v10 = acc[mi][ni][2] + b0, v11 = acc[mi][ni][3] + b1;
            if (ACT == 1) {
                v00 = 0.5f * v00 * (1.0f + erff(v00 * 0.70710678118654752f));
                v01 = 0.5f * v01 * (1.0f + erff(v01 * 0.70710678118654752f));
                v10 = 0.5f * v10 * (1.0f + erff(v10 * 0.70710678118654752f));
                v11 = 0.5f * v11 * (1.0f + erff(v11 * 0.70710678118654752f));
            }
            if (HASRES) {
                float2 r0 = *(const float2*)(res + orow_a * N + col);
                float2 r1 = *(const float2*)(res + orow_b * N + col);
                v00 += r0.x; v01 += r0.y; v10 += r1.x; v11 += r1.y;
            }
            if (ADDPE) {
                float2 p0 = *(const float2*)(pe + (size_t)pes_a * DMODEL + col);
                float2 p1 = *(const float2*)(pe + (size_t)pes_b * DMODEL + col);
                v00 += p0.x; v01 += p0.y; v10 += p1.x; v11 += p1.y;
            }
            if (OUTBF) {
                bf16* C = (bf16*)Cout;
                __nv_bfloat162 p0 = __floats2bfloat162_rn(v00, v01);
                __nv_bfloat162 p1 = __floats2bfloat162_rn(v10, v11);
                *reinterpret_cast<uint32_t*>(C + orow_a * N + col) = *reinterpret_cast<uint32_t*>(&p0);
                *reinterpret_cast<uint32_t*>(C + orow_b * N + col) = *reinterpret_cast<uint32_t*>(&p1);
            } else {
                float* C = (float*)Cout;
                *(float2*)(C + orow_a * N + col) = make_float2(v00, v01);
                *(float2*)(C + orow_b * N + col) = make_float2(v10, v11);
            }
        }
    }
}

// ---------------- LayerNorm: 2 rows per warp, bf16 out ----------------------
__global__ void ln_kernel(const float* __restrict__ x,
                          const float* __restrict__ g,
                          const float* __restrict__ b,
                          bf16* __restrict__ y)
{
    const int warp = threadIdx.x >> 5, lane = threadIdx.x & 31;
    const int row0 = blockIdx.x * 16 + warp * 2;

    const float4* xpA = (const float4*)(x + (size_t)row0 * DMODEL);
    const float4* xpB = (const float4*)(x + (size_t)(row0 + 1) * DMODEL);
    float4 uA = xpA[lane * 2], wA = xpA[lane * 2 + 1];
    float4 uB = xpB[lane * 2], wB = xpB[lane * 2 + 1];

    float sA = uA.x + uA.y + uA.z + uA.w + wA.x + wA.y + wA.z + wA.w;
    float sB = uB.x + uB.y + uB.z + uB.w + wB.x + wB.y + wB.z + wB.w;
#pragma unroll
    for (int off = 16; off; off >>= 1) {
        sA += __shfl_xor_sync(0xffffffffu, sA, off);
        sB += __shfl_xor_sync(0xffffffffu, sB, off);
    }
    float muA = sA * (1.f / DMODEL), muB = sB * (1.f / DMODEL);

    float a0 = uA.x - muA, a1 = uA.y - muA, a2 = uA.z - muA, a3 = uA.w - muA;
    float a4 = wA.x - muA, a5 = wA.y - muA, a6 = wA.z - muA, a7 = wA.w - muA;
    float c0 = uB.x - muB, c1 = uB.y - muB, c2 = uB.z - muB, c3 = uB.w - muB;
    float c4 = wB.x - muB, c5 = wB.y - muB, c6 = wB.z - muB, c7 = wB.w - muB;
    float s2A = a0*a0 + a1*a1 + a2*a2 + a3*a3 + a4*a4 + a5*a5 + a6*a6 + a7*a7;
    float s2B = c0*c0 + c1*c1 + c2*c2 + c3*c3 + c4*c4 + c5*c5 + c6*c6 + c7*c7;
#pragma unroll
    for (int off = 16; off; off >>= 1) {
        s2A += __shfl_xor_sync(0xffffffffu, s2A, off);
        s2B += __shfl_xor_sync(0xffffffffu, s2B, off);
    }
    float invA = rsqrtf(s2A * (1.f / DMODEL) + LNEPS);
    float invB = rsqrtf(s2B * (1.f / DMODEL) + LNEPS);

    const float4* gp = (const float4*)g;
    const float4* bp = (const float4*)b;
    float4 g0 = gp[lane * 2], g1 = gp[lane * 2 + 1];
    float4 b0 = bp[lane * 2], b1 = bp[lane * 2 + 1];

    {
        __nv_bfloat162 p0 = __floats2bfloat162_rn(a0 * invA * g0.x + b0.x, a1 * invA * g0.y + b0.y);
        __nv_bfloat162 p1 = __floats2bfloat162_rn(a2 * invA * g0.z + b0.z, a3 * invA * g0.w + b0.w);
        __nv_bfloat162 p2 = __floats2bfloat162_rn(a4 * invA * g1.x + b1.x, a5 * invA * g1.y + b1.y);
        __nv_bfloat162 p3 = __floats2bfloat162_rn(a6 * invA * g1.z + b1.z, a7 * invA * g1.w + b1.w);
        uint4 o;
        o.x = *reinterpret_cast<uint32_t*>(&p0);
        o.y = *reinterpret_cast<uint32_t*>(&p1);
        o.z = *reinterpret_cast<uint32_t*>(&p2);
        o.w = *reinterpret_cast<uint32_t*>(&p3);
        *reinterpret_cast<uint4*>(y + (size_t)row0 * DMODEL + lane * 8) = o;
    }
    {
        __nv_bfloat162 p0 = __floats2bfloat162_rn(c0 * invB * g0.x + b0.x, c1 * invB * g0.y + b0.y);
        __nv_bfloat162 p1 = __floats2bfloat162_rn(c2 * invB * g0.z + b0.z, c3 * invB * g0.w + b0.w);
        __nv_bfloat162 p2 = __floats2bfloat162_rn(c4 * invB * g1.x + b1.x, c5 * invB * g1.y + b1.y);
        __nv_bfloat162 p3 = __floats2bfloat162_rn(c6 * invB * g1.z + b1.z, c7 * invB * g1.w + b1.w);
        uint4 o;
        o.x = *reinterpret_cast<uint32_t*>(&p0);
        o.y = *reinterpret_cast<uint32_t*>(&p1);
        o.z = *reinterpret_cast<uint32_t*>(&p2);
        o.w = *reinterpret_cast<uint32_t*>(&p3);
        *reinterpret_cast<uint4*>(y + (size_t)(row0 + 1) * DMODEL + lane * 8) = o;
    }
}

// ---------------- fused per-head QKV projection, full SEQ per block ----------
__global__ void qkv_kernel(const bf16* __restrict__ x1,
                           const float* __restrict__ wq, const float* __restrict__ bq,
                           const float* __restrict__ wk, const float* __restrict__ bk,
                           const float* __restrict__ wv, const float* __restrict__ bv,
                           bf16* __restrict__ q, bf16* __restrict__ k, bf16* __restrict__ v)
{
    __shared__ float wqs[32 * 33], wks[32 * 33], wvs[32 * 33];
    __shared__ float bqs[32], bks[32], bvs[32];
    __shared__ float xr[200 * 33];
    const int nh = blockIdx.x;
    const int n = nh / NHEAD, h = nh % NHEAD;
    const int t = threadIdx.x;
    const float* wqg = wq + (size_t)h * DH * DH;
    const float* wkg = wk + (size_t)h * DH * DH;
    const float* wvg = wv + (size_t)h * DH * DH;

    for (int i = t; i < DH * DH; i += 256) {
        int e = i >> 5, d = i & 31;
        wqs[e * 33 + d] = wqg[i];
        wks[e * 33 + d] = wkg[i];
        wvs[e * 33 + d] = wvg[i];
    }
    if (t < 32) { bqs[t] = bq[h * DH + t]; bks[t] = bk[h * DH + t]; bvs[t] = bv[h * DH + t]; }

    for (int i = t; i < SEQ * 32; i += 256) {
        int r = i >> 5, d = i & 31;
        xr[r * 33 + d] = __bfloat162float(x1[((size_t)n * SEQ + r) * DMODEL + h * DH + d]);
    }
    __syncthreads();

    const float scale = 0.17677669529663689f * 1.4426950408889634f;  // log2e/sqrt(32)
    const int wr = (t >> 5) * 25, lane = t & 31;
    const float bqv = bqs[lane], bkv = bks[lane], bvv = bvs[lane];
#pragma unroll 5
    for (int r = 0; r < 25; r++) {
        int s = wr + r;
        if (s >= SEQ) break;
        const float* xp = xr + s * 33;
        float aq = bqv, ak = bkv, av = bvv;
#pragma unroll
        for (int d = 0; d < 32; d++) {
            float xv = xp[d];
            aq += xv * wqs[lane * 33 + d];
            ak += xv * wks[lane * 33 + d];
            av += xv * wvs[lane * 33 + d];
        }
        size_t oidx = ((size_t)nh * SEQ + s) * DH + lane;
        q[oidx] = __float2bfloat16(aq * scale);
        k[oidx] = __float2bfloat16(ak);
        v[oidx] = __float2bfloat16(av);
    }
}

// ---------------- tensor-core flash attention per (n,h), base-2 softmax -----
// kt=0..5 full 32-key tiles (no mask), tail tile 16 keys (rows 192..207, masked).
#define SPAD 208
#define KSTR 20      // u32 per K row (16 data + 4 pad); (20g+q4)%32 conflict-free
#define VSTR 108     // u32 per VT row (104 data + 4 pad); (12g+q4)%32 conflict-free

__global__ void __launch_bounds__(224) attn_tc(const bf16* __restrict__ q,
                                               const bf16* __restrict__ k,
                                               const bf16* __restrict__ v,
                                               bf16* __restrict__ o)
{
    __shared__ uint32_t Ks[SPAD * KSTR];      // 16640 B
    __shared__ uint32_t VT[32 * VSTR];        // 13824 B  (total 29.75 KB)

    const int nh = blockIdx.x;
    const int n = nh / NHEAD, h = nh % NHEAD;
    const int t = threadIdx.x, warp = t >> 5, lane = t & 31;
    const int g = lane >> 2, q4 = lane & 3;
    const size_t base = (size_t)nh * SEQ * DH;
    const uint32_t* q32 = (const uint32_t*)(q + base);
    const uint32_t* k32 = (const uint32_t*)(k + base);
    const uint32_t* v32 = (const uint32_t*)(v + base);

    for (int i = t; i < SPAD * 16; i += 224) {
        int r = i >> 4, c = i & 15;
        Ks[r * KSTR + c] = (r < SEQ) ? k32[r * 16 + c] : 0u;
    }
    bf16* VT16 = (bf16*)VT;
    for (int i = t; i < SPAD * 16; i += 224) {
        int tt = i >> 4, c = i & 15;
        uint32_t val = (tt < SEQ) ? v32[tt * 16 + c] : 0u;
        __nv_bfloat162 pr = *reinterpret_cast<__nv_bfloat162*>(&val);
        VT16[(2 * c)     * (VSTR * 2) + tt] = pr.x;
        VT16[(2 * c + 1) * (VSTR * 2) + tt] = pr.y;
    }
    __syncthreads();

    const int qbase = warp * 32;
    uint32_t qf[2][2][4];
#pragma unroll
    for (int mi = 0; mi < 2; mi++) {
        int r0 = qbase + mi * 16 + g, r1 = r0 + 8;
        bool v0 = r0 < SEQ, v1 = r1 < SEQ;
#pragma unroll
        for (int ks = 0; ks < 2; ks++) {
            qf[mi][ks][0] = v0 ? q32[r0 * 16 + ks * 8 + q4]     : 0u;
            qf[mi][ks][1] = v1 ? q32[r1 * 16 + ks * 8 + q4]     : 0u;
            qf[mi][ks][2] = v0 ? q32[r0 * 16 + ks * 8 + q4 + 4] : 0u;
            qf[mi][ks][3] = v1 ? q32[r1 * 16 + ks * 8 + q4 + 4] : 0u;
        }
    }

    float Oa[2][4][4];
#pragma unroll
    for (int mi = 0; mi < 2; mi++)
#pragma unroll
        for (int ne = 0; ne < 4; ne++)
#pragma unroll
            for (int e = 0; e < 4; e++) Oa[mi][ne][e] = 0.f;
    float m_[2][2] = {{-1e30f, -1e30f}, {-1e30f, -1e30f}};
    float l_[2][2] = {{0.f, 0.f}, {0.f, 0.f}};

    // ---- full 32-key tiles, kt = 0..5, no masking ----
    for (int kt = 0; kt < 6; kt++) {
        float sc[2][4][4];
#pragma unroll
        for (int mi = 0; mi < 2; mi++)
#pragma unroll
            for (int ni = 0; ni < 4; ni++)
#pragma unroll
                for (int e = 0; e < 4; e++) sc[mi][ni][e] = 0.f;

        uint32_t kf[2][4][2];
#pragma unroll
        for (int ks = 0; ks < 2; ks++)
#pragma unroll
            for (int ni = 0; ni < 4; ni++) {
                int r = kt * 32 + ni * 8 + g;
                kf[ks][ni][0] = Ks[r * KSTR + ks * 8 + q4];
                kf[ks][ni][1] = Ks[r * KSTR + ks * 8 + q4 + 4];
            }
#pragma unroll
        for (int mi = 0; mi < 2; mi++)
#pragma unroll
            for (int ni = 0; ni < 4; ni++)
#pragma unroll
                for (int ks = 0; ks < 2; ks++)
                    mma_bf16(sc[mi][ni], qf[mi][ks], kf[ks][ni]);

#pragma unroll
        for (int mi = 0; mi < 2; mi++) {
#pragma unroll
            for (int hf = 0; hf < 2; hf++) {
                float mx = fmaxf(fmaxf(sc[mi][0][hf * 2], sc[mi][0][hf * 2 + 1]),
                                 fmaxf(sc[mi][1][hf * 2], sc[mi][1][hf * 2 + 1]));
                mx = fmaxf(mx, fmaxf(fmaxf(sc[mi][2][hf * 2], sc[mi][2][hf * 2 + 1]),
                                     fmaxf(sc[mi][3][hf * 2], sc[mi][3][hf * 2 + 1])));
                mx = fmaxf(mx, __shfl_xor_sync(0xffffffffu, mx, 1));
                mx = fmaxf(mx, __shfl_xor_sync(0xffffffffu, mx, 2));
                float mnew = fmaxf(m_[mi][hf], mx);
                float f = ex2f(m_[mi][hf] - mnew);
                m_[mi][hf] = mnew;
                float rs = 0.f;
#pragma unroll
                for (int ni = 0; ni < 4; ni++) {
                    float p0 = ex2f(sc[mi][ni][hf * 2]     - mnew);
                    float p1 = ex2f(sc[mi][ni][hf * 2 + 1] - mnew);
                    sc[mi][ni][hf * 2]     = p0;
                    sc[mi][ni][hf * 2 + 1] = p1;
                    rs += p0 + p1;
                }
                rs += __shfl_xor_sync(0xffffffffu, rs, 1);
                rs += __shfl_xor_sync(0xffffffffu, rs, 2);
                l_[mi][hf] = l_[mi][hf] * f + rs;
#pragma unroll
                for (int ne = 0; ne < 4; ne++) {
                    Oa[mi][ne][hf * 2]     *= f;
                    Oa[mi][ne][hf * 2 + 1] *= f;
                }
            }
        }

        uint32_t pa[2][2][4];
#pragma unroll
        for (int mi = 0; mi < 2; mi++)
#pragma unroll
            for (int ks = 0; ks < 2; ks++) {
                __nv_bfloat162 t0 = __floats2bfloat162_rn(sc[mi][2 * ks][0],     sc[mi][2 * ks][1]);
                __nv_bfloat162 t1 = __floats2bfloat162_rn(sc[mi][2 * ks][2],     sc[mi][2 * ks][3]);
                __nv_bfloat162 t2 = __floats2bfloat162_rn(sc[mi][2 * ks + 1][0], sc[mi][2 * ks + 1][1]);
                __nv_bfloat162 t3 = __floats2bfloat162_rn(sc[mi][2 * ks + 1][2], sc[mi][2 * ks + 1][3]);
                pa[mi][ks][0] = *reinterpret_cast<uint32_t*>(&t0);
                pa[mi][ks][1] = *reinterpret_cast<uint32_t*>(&t1);
                pa[mi][ks][2] = *reinterpret_cast<uint32_t*>(&t2);
                pa[mi][ks][3] = *reinterpret_cast<uint32_t*>(&t3);
            }

        uint32_t vf[2][4][2];
#pragma unroll
        for (int ks = 0; ks < 2; ks++)
#pragma unroll
            for (int ne = 0; ne < 4; ne++) {
                int r = ne * 8 + g;
                int cu = kt * 16 + ks * 8 + q4;
                vf[ks][ne][0] = VT[r * VSTR + cu];
                vf[ks][ne][1] = VT[r * VSTR + cu + 4];
            }
#pragma unroll
        for (int mi = 0; mi < 2; mi++)
#pragma unroll
            for (int ne = 0; ne < 4; ne++)
#pragma unroll
                for (int ks = 0; ks < 2; ks++)
                    mma_bf16(Oa[mi][ne], pa[mi][ks], vf[ks][ne]);
    }

    // ---- tail tile: 16 keys (rows 192..207), masked at >= SEQ ----
    {
        float sc[2][2][4];
#pragma unroll
        for (int mi = 0; mi < 2; mi++)
#pragma unroll
            for (int ni = 0; ni < 2; ni++)
#pragma unroll
                for (int e = 0; e < 4; e++) sc[mi][ni][e] = 0.f;

        uint32_t kf[2][2][2];
#pragma unroll
        for (int ks = 0; ks < 2; ks++)
#pragma unroll
            for (int ni = 0; ni < 2; ni++) {
                int r = 192 + ni * 8 + g;
                kf[ks][ni][0] = Ks[r * KSTR + ks * 8 + q4];
                kf[ks][ni][1] = Ks[r * KSTR + ks * 8 + q4 + 4];
            }
#pragma unroll
        for (int mi = 0; mi < 2; mi++)
#pragma unroll
            for (int ni = 0; ni < 2; ni++)
#pragma unroll
                for (int ks = 0; ks < 2; ks++)
                    mma_bf16(sc[mi][ni], qf[mi][ks], kf[ks][ni]);

        // mask cols >= SEQ
#pragma unroll
        for (int mi = 0; mi < 2; mi++)
#pragma unroll
            for (int ni = 0; ni < 2; ni++) {
                int col = 192 + ni * 8 + q4 * 2;
#pragma unroll
                for (int hf = 0; hf < 2; hf++) {
                    if (col     >= SEQ) sc[mi][ni][hf * 2]     = -1e30f;
                    if (col + 1 >= SEQ) sc[mi][ni][hf * 2 + 1] = -1e30f;
                }
            }

#pragma unroll
        for (int mi = 0; mi < 2; mi++) {
#pragma unroll
            for (int hf = 0; hf < 2; hf++) {
                float mx = fmaxf(fmaxf(sc[mi][0][hf * 2], sc[mi][0][hf * 2 + 1]),
                                 fmaxf(sc[mi][1][hf * 2], sc[mi][1][hf * 2 + 1]));
                mx = fmaxf(mx, __shfl_xor_sync(0xffffffffu, mx, 1));
                mx = fmaxf(mx, __shfl_xor_sync(0xffffffffu, mx, 2));
                float mnew = fmaxf(m_[mi][hf], mx);
                float f = ex2f(m_[mi][hf] - mnew);
                m_[mi][hf] = mnew;
                float rs = 0.f;
#pragma unroll
                for (int ni = 0; ni < 2; ni++) {
                    float p0 = ex2f(sc[mi][ni][hf * 2]     - mnew);
                    float p1 = ex2f(sc[mi][ni][hf * 2 + 1] - mnew);
                    sc[mi][ni][hf * 2]     = p0;
                    sc[mi][ni][hf * 2 + 1] = p1;
                    rs += p0 + p1;
                }
                rs += __shfl_xor_sync(0xffffffffu, rs, 1);
                rs += __shfl_xor_sync(0xffffffffu, rs, 2);
                l_[mi][hf] = l_[mi][hf] * f + rs;
#pragma unroll
                for (int ne = 0; ne < 4; ne++) {
                    Oa[mi][ne][hf * 2]     *= f;
                    Oa[mi][ne][hf * 2 + 1] *= f;
                }
            }
        }

        uint32_t pa[2][4];
#pragma unroll
        for (int mi = 0; mi < 2; mi++) {
            __nv_bfloat162 t0 = __floats2bfloat162_rn(sc[mi][0][0], sc[mi][0][1]);
            __nv_bfloat162 t1 = __floats2bfloat162_rn(sc[mi][0][2], sc[mi][0][3]);
            __nv_bfloat162 t2 = __floats2bfloat162_rn(sc[mi][1][0], sc[mi][1][1]);
            __nv_bfloat162 t3 = __floats2bfloat162_rn(sc[mi][1][2], sc[mi][1][3]);
            pa[mi][0] = *reinterpret_cast<uint32_t*>(&t0);
            pa[mi][1] = *reinterpret_cast<uint32_t*>(&t1);
            pa[mi][2] = *reinterpret_cast<uint32_t*>(&t2);
            pa[mi][3] = *reinterpret_cast<uint32_t*>(&t3);
        }

        uint32_t vf[4][2];
#pragma unroll
        for (int ne = 0; ne < 4; ne++) {
            int r = ne * 8 + g;
            int cu = 96 + q4;
            vf[ne][0] = VT[r * VSTR + cu];
            vf[ne][1] = VT[r * VSTR + cu + 4];
        }
#pragma unroll
        for (int mi = 0; mi < 2; mi++)
#pragma unroll
            for (int ne = 0; ne < 4; ne++)
                mma_bf16(Oa[mi][ne], pa[mi], vf[ne]);
    }

#pragma unroll
    for (int mi = 0; mi < 2; mi++) {
#pragma unroll
        for (int hf = 0; hf < 2; hf++) {
            int row = qbase + mi * 16 + hf * 8 + g;
            if (row >= SEQ) continue;
            float inv = 1.f / l_[mi][hf];
            bf16* op = o + ((size_t)n * SEQ + row) * DMODEL + h * DH;
#pragma unroll
            for (int ne = 0; ne < 4; ne++) {
                __nv_bfloat162 p = __floats2bfloat162_rn(Oa[mi][ne][hf * 2] * inv,
                                                         Oa[mi][ne][hf * 2 + 1] * inv);
                *reinterpret_cast<uint32_t*>(op + ne * 8 + q4 * 2) = *reinterpret_cast<uint32_t*>(&p);
            }
        }
    }
}

// ---------------- softmax over precomputed logits ---------------------------
__global__ void softmax_head_kernel(const float* __restrict__ logits_in,
                                    float* __restrict__ out)
{
    __shared__ float logits[OUTC];
    __shared__ float red[8];
    const int n = blockIdx.x;
    const int t = threadIdx.x, wid = t >> 5, lane = t & 31;

    for (int j = t; j < OUTC; j += 256) logits[j] = logits_in[(size_t)n * OUTP + j];
    __syncthreads();

    float mx = -1e30f;
    for (int j = t; j < OUTC; j += 256) mx = fmaxf(mx, logits[j]);
#pragma unroll
    for (int off = 16; off; off >>= 1) mx = fmaxf(mx, __shfl_xor_sync(0xffffffffu, mx, off));
    if (lane == 0) red[wid] = mx;
    __syncthreads();
    float bm = -1e30f;
#pragma unroll
    for (int i = 0; i < 8; i++) bm = fmaxf(bm, red[i]);
    __syncthreads();

    float sum = 0.f;
    for (int j = t; j < OUTC; j += 256) {
        float e = __expf(logits[j] - bm);
        logits[j] = e;
        sum += e;
    }
#pragma unroll
    for (int off = 16; off; off >>= 1) sum += __shfl_xor_sync(0xffffffffu, sum, off);
    if (lane == 0) red[wid] = sum;
    __syncthreads();
    float bs = 0.f;
#pragma unroll
    for (int i = 0; i < 8; i++) bs += red[i];
    float inv = 1.f / bs;
    __syncthreads();
    for (int j = t; j < OUTC; j += 256) out[(size_t)n * OUTC + j] = logits[j] * inv;
}

// ---------------- launcher ----------------
extern "C" void kernel_launch(void* const* d_in, const int* in_sizes, int n_in,
                              void* d_out, int out_size)
{
    const float* images  = (const float*)d_in[0];
    const float* w_map   = (const float*)d_in[1];
    const float* b_map   = (const float*)d_in[2];
    const float* cls_tok = (const float*)d_in[3];
    const float* norm1_g = (const float*)d_in[4];
    const float* norm1_b = (const float*)d_in[5];
    const float* wq      = (const float*)d_in[6];
    const float* bq      = (const float*)d_in[7];
    const float* wk      = (const float*)d_in[8];
    const float* bk      = (const float*)d_in[9];
    const float* wv      = (const float*)d_in[10];
    const float* bv      = (const float*)d_in[11];
    const float* w_last  = (const float*)d_in[12];
    const float* b_last  = (const float*)d_in[13];
    const float* norm2_g = (const float*)d_in[14];
    const float* norm2_b = (const float*)d_in[15];
    const float* w_mlp1  = (const float*)d_in[16];
    const float* b_mlp1  = (const float*)d_in[17];
    const float* w_mlp2  = (const float*)d_in[18];
    const float* b_mlp2  = (const float*)d_in[19];
    const float* w_out   = (const float*)d_in[20];
    const float* b_out   = (const float*)d_in[21];
    float* out = (float*)d_out;

    bf16 *patches, *x1b, *qb, *kb, *vb, *ob, *h1b;
    bf16 *wmapb, *wlastb, *wmlp1b, *wmlp2b, *wcat, *ccat;
    float *X, *pe, *bout_pad, *logits;
    cudaGetSymbolAddress((void**)&patches, g_patches_b);
    cudaGetSymbolAddress((void**)&X,   g_X);
    cudaGetSymbolAddress((void**)&x1b, g_x1b);
    cudaGetSymbolAddress((void**)&qb,  g_qb);
    cudaGetSymbolAddress((void**)&kb,  g_kb);
    cudaGetSymbolAddress((void**)&vb,  g_vb);
    cudaGetSymbolAddress((void**)&ob,  g_ob);
    cudaGetSymbolAddress((void**)&h1b, g_h1b);
    cudaGetSymbolAddress((void**)&pe,  g_pe);
    cudaGetSymbolAddress((void**)&wmapb,  g_wmapb);
    cudaGetSymbolAddress((void**)&wlastb, g_wlastb);
    cudaGetSymbolAddress((void**)&wmlp1b, g_wmlp1b);
    cudaGetSymbolAddress((void**)&wmlp2b, g_wmlp2b);
    cudaGetSymbolAddress((void**)&wcat, g_wout_cat);
    cudaGetSymbolAddress((void**)&ccat, g_cls_cat);
    cudaGetSymbolAddress((void**)&bout_pad, g_bout_pad);
    cudaGetSymbolAddress((void**)&logits,   g_logits);

    cudaFuncSetAttribute(gemm_bf<0, false, false, true >, cudaFuncAttributeMaxDynamicSharedMemorySize, GEMM_SMEM);
    cudaFuncSetAttribute(gemm_bf<0, true,  false, false>, cudaFuncAttributeMaxDynamicSharedMemorySize, GEMM_SMEM);
    cudaFuncSetAttribute(gemm_bf<1, false, true,  false>, cudaFuncAttributeMaxDynamicSharedMemorySize, GEMM_SMEM);
    cudaFuncSetAttribute(gemm_bf<0, false, false, false>, cudaFuncAttributeMaxDynamicSharedMemorySize, GEMM_SMEM);

    // 0) weight conversion to bf16 (+ concatenated head weights)
    {
        int n0 = DMODEL * IN_D;
        int n1 = NLAYER * DMODEL * DMODEL;
        int n3 = NLAYER * 4 * DMODEL * DMODEL;
        int totf4 = (n0 + n1 + 2 * n3) / 4;
        cvt_all_kernel<<<(totf4 + 255) / 256, 256>>>(
            w_map, wmapb, n0, w_last, wlastb, n1,
            w_mlp1, wmlp1b, n3, w_mlp2, wmlp2b, n3);
        int hw = OUTP * DMODEL / 4;
        cvt_head_kernel<<<(hw + 255) / 256, 256>>>(w_out, b_out, wcat, bout_pad);
    }

    // 1) patches + PE table
    {
        int tot = BATCH * NP * IN_D / 4;
        patch_kernel<<<(tot + 255) / 256, 256>>>(images, patches);
        int pt = SEQ * DMODEL;
        pe_kernel<<<(pt + 255) / 256, 256>>>(pe);
    }

    // 2) patch-embed GEMM fused with assemble
    gemm_bf<0, false, false, true><<<dim3(DMODEL / 128, (BATCH * NP) / 128), 256, GEMM_SMEM>>>(
        patches, wmapb, b_map, nullptr, pe, X, BATCH * NP, DMODEL, IN_D);

    // 2b) cls rows
    cls_kernel<<<(BATCH * DMODEL + 255) / 256, 256>>>(cls_tok, pe, X);

    const int MROWS = BATCH * SEQ;   // 25216 = 16*1576

    for (int l = 0; l < NLAYER; l++) {
        ln_kernel<<<MROWS / 16, 256>>>(X, norm1_g + l * DMODEL, norm1_b + l * DMODEL, x1b);

        qkv_kernel<<<BATCH * NHEAD, 256>>>(
            x1b,
            wq + (size_t)l * NHEAD * DH * DH, bq + (size_t)l * NHEAD * DH,
            wk + (size_t)l * NHEAD * DH * DH, bk + (size_t)l * NHEAD * DH,
            wv + (size_t)l * NHEAD * DH * DH, bv + (size_t)l * NHEAD * DH,
            qb, kb, vb);

        attn_tc<<<BATCH * NHEAD, 224>>>(qb, kb, vb, ob);

        gemm_bf<0, true, false, false><<<dim3(DMODEL / 128, MROWS / 128), 256, GEMM_SMEM>>>(
            ob, wlastb + (size_t)l * DMODEL * DMODEL, b_last + l * DMODEL, X, nullptr, X,
            MROWS, DMODEL, DMODEL);

        ln_kernel<<<MROWS / 16, 256>>>(X, norm2_g + l * DMODEL, norm2_b + l * DMODEL, x1b);

        gemm_bf<1, false, true, false><<<dim3((4 * DMODEL) / 128, MROWS / 128), 256, GEMM_SMEM>>>(
            x1b, wmlp1b + (size_t)l * 4 * DMODEL * DMODEL, b_mlp1 + l * 4 * DMODEL,
            nullptr, nullptr, h1b, MROWS, 4 * DMODEL, DMODEL);

        gemm_bf<0, true, false, false><<<dim3(DMODEL / 128, MROWS / 128), 256, GEMM_SMEM>>>(
            h1b, wmlp2b + (size_t)l * 4 * DMODEL * DMODEL, b_mlp2 + l * DMODEL, X, nullptr, X,
            MROWS, DMODEL, 4 * DMODEL);
    }

    // head: cls concat extraction -> single compensated bf16 GEMM (K=768) -> softmax
    cls_extract_kernel<<<(BATCH * DMODEL / 4 + 255) / 256, 256>>>(X, ccat);
    gemm_bf<0, false, false, false><<<dim3(OUTP / 128, BATCH / 128), 256, GEMM_SMEM>>>(
        ccat, wcat, bout_pad, nullptr, nullptr, logits, BATCH, OUTP, HKDIM);
    softmax_head_kernel<<<BATCH, 256>>>(logits, out);
}

// round 17
// speedup vs baseline: 1.5114x; 1.5114x over previous
#include <cuda_runtime.h>
#include <cuda_bf16.h>
#include <math.h>
#include <stdint.h>

// ---------------- problem constants ----------------
#define BATCH 128
#define CH    3
#define HIM   224
#define PGRID 14
#define NP    196
#define PATCH 16
#define IN_D  768
#define DMODEL 256
#define NHEAD 8
#define DH    32
#define NLAYER 4
#define SEQ   197
#define OUTC  1000
#define OUTP  1024
#define HKDIM 768            // head GEMM K = 3*DMODEL
#define LNEPS 1e-5f

typedef __nv_bfloat16 bf16;

// ---------------- scratch (device globals) ----------------
__device__ bf16  g_patches_b[BATCH * NP * IN_D];
__device__ float g_X [BATCH * SEQ * DMODEL];
__device__ bf16  g_x1b[BATCH * SEQ * DMODEL];
__device__ bf16  g_qb [BATCH * SEQ * DMODEL];             // [n,h,s,e] (pre-scaled by scale*log2e)
__device__ bf16  g_kb [BATCH * SEQ * DMODEL];
__device__ bf16  g_vb [BATCH * SEQ * DMODEL];
__device__ bf16  g_ob [BATCH * SEQ * DMODEL];             // [n,s,d]
__device__ bf16  g_h1b[BATCH * SEQ * 4 * DMODEL];
__device__ float g_pe[SEQ * DMODEL];
__device__ bf16  g_wmapb [DMODEL * IN_D];
__device__ bf16  g_wlastb[NLAYER * DMODEL * DMODEL];
__device__ bf16  g_wmlp1b[NLAYER * 4 * DMODEL * DMODEL];
__device__ bf16  g_wmlp2b[NLAYER * 4 * DMODEL * DMODEL];
__device__ bf16  g_wout_cat[OUTP * HKDIM];                // [whi | wlo | whi]
__device__ float g_bout_pad[OUTP];
__device__ bf16  g_cls_cat[BATCH * HKDIM];                // [chi | chi | clo]
__device__ float g_logits[BATCH * OUTP];

__device__ __forceinline__ float ex2f(float x)
{
    float r;
    asm("ex2.approx.f32 %0, %1;" : "=f"(r) : "f"(x));
    return r;
}

// ---------------- fp32 -> bf16 convert, all weights in one launch ----------
__device__ __forceinline__ void cvt4(const float* __restrict__ s, bf16* __restrict__ d, int i)
{
    float4 v = *(const float4*)(s + i);
    __nv_bfloat162 p0 = __floats2bfloat162_rn(v.x, v.y);
    __nv_bfloat162 p1 = __floats2bfloat162_rn(v.z, v.w);
    uint2 o;
    o.x = *reinterpret_cast<uint32_t*>(&p0);
    o.y = *reinterpret_cast<uint32_t*>(&p1);
    *reinterpret_cast<uint2*>(d + i) = o;
}

__global__ void cvt_all_kernel(const float* __restrict__ s0, bf16* __restrict__ d0, int n0,
                               const float* __restrict__ s1, bf16* __restrict__ d1, int n1,
                               const float* __restrict__ s2, bf16* __restrict__ d2, int n2,
                               const float* __restrict__ s3, bf16* __restrict__ d3, int n3)
{
    int i = (blockIdx.x * 256 + threadIdx.x) * 4;
    if (i < n0) { cvt4(s0, d0, i); return; }
    i -= n0;
    if (i < n1) { cvt4(s1, d1, i); return; }
    i -= n1;
    if (i < n2) { cvt4(s2, d2, i); return; }
    i -= n2;
    if (i < n3) { cvt4(s3, d3, i); return; }
}

// ---------------- head weight: pad + hi/lo split -> concat [whi|wlo|whi] ----
__global__ void cvt_head_kernel(const float* __restrict__ w_out, const float* __restrict__ b_out,
                                bf16* __restrict__ wcat, float* __restrict__ bpad)
{
    int tid = blockIdx.x * 256 + threadIdx.x;
    int i = tid * 4;
    if (i < OUTP * DMODEL) {
        int row = i / DMODEL, col = i % DMODEL;
        bf16* wr = wcat + (size_t)row * HKDIM;
        if (row < OUTC) {
            float4 v = *(const float4*)(w_out + i);
            bf16 h0 = __float2bfloat16(v.x), h1 = __float2bfloat16(v.y);
            bf16 h2 = __float2bfloat16(v.z), h3 = __float2bfloat16(v.w);
            bf16 l0 = __float2bfloat16(v.x - __bfloat162float(h0));
            bf16 l1 = __float2bfloat16(v.y - __bfloat162float(h1));
            bf16 l2 = __float2bfloat16(v.z - __bfloat162float(h2));
            bf16 l3 = __float2bfloat16(v.w - __bfloat162float(h3));
            wr[col]     = h0; wr[col + 1] = h1; wr[col + 2] = h2; wr[col + 3] = h3;
            wr[DMODEL + col]     = l0; wr[DMODEL + col + 1] = l1;
            wr[DMODEL + col + 2] = l2; wr[DMODEL + col + 3] = l3;
            wr[2 * DMODEL + col]     = h0; wr[2 * DMODEL + col + 1] = h1;
            wr[2 * DMODEL + col + 2] = h2; wr[2 * DMODEL + col + 3] = h3;
        } else {
            uint2 z = {0u, 0u};
            *reinterpret_cast<uint2*>(wr + col) = z;
            *reinterpret_cast<uint2*>(wr + DMODEL + col) = z;
            *reinterpret_cast<uint2*>(wr + 2 * DMODEL + col) = z;
        }
    }
    if (tid < OUTP) bpad[tid] = (tid < OUTC) ? b_out[tid] : 0.f;
}

// ---------------- cls row extraction -> concat [chi|chi|clo] ----------------
__global__ void cls_extract_kernel(const float* __restrict__ X, bf16* __restrict__ ccat)
{
    int i = (blockIdx.x * 256 + threadIdx.x) * 4;
    if (i >= BATCH * DMODEL) return;
    int n = i / DMODEL, d = i % DMODEL;
    float4 v = *(const float4*)(X + (size_t)n * SEQ * DMODEL + d);
    bf16 h0 = __float2bfloat16(v.x), h1 = __float2bfloat16(v.y);
    bf16 h2 = __float2bfloat16(v.z), h3 = __float2bfloat16(v.w);
    bf16 l0 = __float2bfloat16(v.x - __bfloat162float(h0));
    bf16 l1 = __float2bfloat16(v.y - __bfloat162float(h1));
    bf16 l2 = __float2bfloat16(v.z - __bfloat162float(h2));
    bf16 l3 = __float2bfloat16(v.w - __bfloat162float(h3));
    bf16* cr = ccat + (size_t)n * HKDIM;
    cr[d]     = h0; cr[d + 1] = h1; cr[d + 2] = h2; cr[d + 3] = h3;
    cr[DMODEL + d]     = h0; cr[DMODEL + d + 1] = h1;
    cr[DMODEL + d + 2] = h2; cr[DMODEL + d + 3] = h3;
    cr[2 * DMODEL + d]     = l0; cr[2 * DMODEL + d + 1] = l1;
    cr[2 * DMODEL + d + 2] = l2; cr[2 * DMODEL + d + 3] = l3;
}

// ---------------- patch extraction (2x float4 gather, writes bf16) ---------
__global__ void patch_kernel(const float* __restrict__ img, bf16* __restrict__ out)
{
    int tid = blockIdx.x * 256 + threadIdx.x;
    int idx = tid * 8;
    if (idx >= BATCH * NP * IN_D) return;
    int i = idx % IN_D;
    int p = (idx / IN_D) % NP;
    int n = idx / (IN_D * NP);
    int c   = i >> 8;
    int r   = (i >> 4) & 15;
    int col = i & 15;               // 0 or 8
    int py = p / PGRID, px = p % PGRID;
    const float* src = img + (((size_t)n * CH + c) * HIM + py * PATCH + r) * HIM
                           + px * PATCH + col;
    float4 v0 = *(const float4*)(src);
    float4 v1 = *(const float4*)(src + 4);
    __nv_bfloat162 p0 = __floats2bfloat162_rn(v0.x, v0.y);
    __nv_bfloat162 p1 = __floats2bfloat162_rn(v0.z, v0.w);
    __nv_bfloat162 p2 = __floats2bfloat162_rn(v1.x, v1.y);
    __nv_bfloat162 p3 = __floats2bfloat162_rn(v1.z, v1.w);
    uint4 o;
    o.x = *reinterpret_cast<uint32_t*>(&p0);
    o.y = *reinterpret_cast<uint32_t*>(&p1);
    o.z = *reinterpret_cast<uint32_t*>(&p2);
    o.w = *reinterpret_cast<uint32_t*>(&p3);
    *reinterpret_cast<uint4*>(out + idx) = o;
}

// ---------------- positional encoding (fp32) ----------------
__global__ void pe_kernel(float* __restrict__ pe)
{
    int i = blockIdx.x * 256 + threadIdx.x;
    if (i >= SEQ * DMODEL) return;
    int s = i / DMODEL, d = i % DMODEL;
    float expo = (float)(2 * (d / 2)) * (1.0f / DMODEL);
    float ang  = (float)s * powf(10000.0f, -expo);
    pe[i] = (d & 1) ? cosf(ang) : sinf(ang);
}

// ---------------- cls rows: X[n][0][:] = cls + pe[0] ------------------------
__global__ void cls_kernel(const float* __restrict__ cls,
                           const float* __restrict__ pe,
                           float* __restrict__ X)
{
    int i = blockIdx.x * 256 + threadIdx.x;
    if (i >= BATCH * DMODEL) return;
    int d = i % DMODEL;
    int n = i / DMODEL;
    X[(size_t)n * SEQ * DMODEL + d] = cls[d] + pe[d];
}

// ---------------- bf16 MMA / ldmatrix helpers -------------------------------
__device__ __forceinline__ void mma_bf16(float* c, const uint32_t* a, const uint32_t* b)
{
    asm volatile(
        "mma.sync.aligned.m16n8k16.row.col.f32.bf16.bf16.f32 "
        "{%0,%1,%2,%3}, {%4,%5,%6,%7}, {%8,%9}, {%0,%1,%2,%3};"
        : "+f"(c[0]), "+f"(c[1]), "+f"(c[2]), "+f"(c[3])
        : "r"(a[0]), "r"(a[1]), "r"(a[2]), "r"(a[3]), "r"(b[0]), "r"(b[1]));
}

#define LDSM4(r0, r1, r2, r3, addr) \
    asm volatile("ldmatrix.sync.aligned.m8n8.x4.shared.b16 {%0,%1,%2,%3}, [%4];" \
                 : "=r"(r0), "=r"(r1), "=r"(r2), "=r"(r3) : "r"(addr))

#define CP16(dst, src) asm volatile("cp.async.cg.shared.global [%0], [%1], 16;\n" :: "r"(dst), "l"(src))
#define CP_COMMIT()    asm volatile("cp.async.commit_group;\n" ::)
#define CP_WAIT1()     asm volatile("cp.async.wait_group 1;\n" ::)
#define CP_WAIT0()     asm volatile("cp.async.wait_group 0;\n" ::)

// ---------------- bf16 tensor-core GEMM, 128x128 tile (frozen config) -------
#define STR 36
#define ABUF (128 * STR)
#define GEMM_SMEM (4 * ABUF * 4)

template<int ACT, bool HASRES, bool OUTBF, bool ADDPE>
__global__ void __launch_bounds__(256) gemm_bf(const bf16* __restrict__ A,
                                               const bf16* __restrict__ W,
                                               const float* __restrict__ bias,
                                               const float* __restrict__ res,
                                               const float* __restrict__ pe,
                                               void* __restrict__ Cout,
                                               int M, int N, int K)
{
    extern __shared__ uint32_t sm_[];
    const uint32_t smem_byte = (uint32_t)__cvta_generic_to_shared(sm_);

    const int t    = threadIdx.x;
    const int warp = t >> 5, lane = t & 31;
    const int g    = lane >> 2, q4 = lane & 3;
    const int warp_m = (warp >> 1) * 32;
    const int warp_n = (warp & 1) * 64;
    const int row0 = blockIdx.y * 128, col0 = blockIdx.x * 128;

    float acc[2][8][4];
#pragma unroll
    for (int mi = 0; mi < 2; mi++)
#pragma unroll
        for (int ni = 0; ni < 8; ni++)
#pragma unroll
            for (int e = 0; e < 4; e++) acc[mi][ni][e] = 0.f;

    auto stage = [&](int k0, int buf) {
        uint32_t abase = smem_byte + buf * (ABUF * 4);
        uint32_t bbase = smem_byte + (2 + buf) * (ABUF * 4);
#pragma unroll
        for (int i = 0; i < 4; i++) {
            int c = t + i * 256;
            int r = c >> 3, co = c & 7;
            CP16(abase + (r * STR + co * 4) * 4, A + (size_t)(row0 + r) * K + k0 + co * 8);
            CP16(bbase + (r * STR + co * 4) * 4, W + (size_t)(col0 + r) * K + k0 + co * 8);
        }
        CP_COMMIT();
    };

    uint32_t a_addr[2][2], b_addr[2][4];
    {
        int ar = warp_m + (lane & 15);
        int ab = (lane >> 4) * 16;
        int br = warp_n + ((lane >> 4) & 1) * 8 + (lane & 7);
        int bb = ((lane >> 3) & 1) * 16;
#pragma unroll
        for (int buf = 0; buf < 2; buf++) {
            uint32_t abase = smem_byte + buf * (ABUF * 4);
            uint32_t bbase = smem_byte + (2 + buf) * (ABUF * 4);
#pragma unroll
            for (int mi = 0; mi < 2; mi++)
                a_addr[buf][mi] = abase + (ar + mi * 16) * (STR * 4) + ab;
#pragma unroll
            for (int nj = 0; nj < 4; nj++)
                b_addr[buf][nj] = bbase + (br + nj * 16) * (STR * 4) + bb;
        }
    }

    const int KT = K >> 6;
    stage(0, 0);

    for (int kt = 0; kt < KT; kt++) {
        const int cur = kt & 1;
        if (kt + 1 < KT) { stage((kt + 1) << 6, cur ^ 1); CP_WAIT1(); }
        else             { CP_WAIT0(); }
        __syncthreads();

#pragma unroll
        for (int ks = 0; ks < 4; ks++) {
            const uint32_t kb = ks * 32;
            uint32_t af[2][4];
            LDSM4(af[0][0], af[0][1], af[0][2], af[0][3], a_addr[cur][0] + kb);
            LDSM4(af[1][0], af[1][1], af[1][2], af[1][3], a_addr[cur][1] + kb);
            uint32_t bf_[8][2];
#pragma unroll
            for (int nj = 0; nj < 4; nj++)
                LDSM4(bf_[2 * nj][0], bf_[2 * nj][1], bf_[2 * nj + 1][0], bf_[2 * nj + 1][1],
                      b_addr[cur][nj] + kb);
#pragma unroll
            for (int mi = 0; mi < 2; mi++)
#pragma unroll
                for (int ni = 0; ni < 8; ni++)
                    mma_bf16(acc[mi][ni], af[mi], bf_[ni]);
        }
        __syncthreads();
    }

#pragma unroll
    for (int mi = 0; mi < 2; mi++) {
        int ra = row0 + warp_m + mi * 16 + g;
        int rb = ra + 8;
        size_t orow_a, orow_b;
        if (ADDPE) {
            orow_a = (size_t)(ra / NP) * SEQ + (ra % NP) + 1;
            orow_b = (size_t)(rb / NP) * SEQ + (rb % NP) + 1;
        } else {
            orow_a = ra; orow_b = rb;
        }
        int pes_a = ADDPE ? ((ra % NP) + 1) : 0;
        int pes_b = ADDPE ? ((rb % NP) + 1) : 0;
#pragma unroll
        for (int ni = 0; ni < 8; ni++) {
            int col = col0 + warp_n + ni * 8 + q4 * 2;
            float b0 = bias[col], b1 = bias[col + 1];
            float v00 = acc[mi][ni][0] + b0, v01 = acc[mi][ni][1] + b1;
            float v10 = acc[mi][ni][2] + b0, v11 = acc[mi][ni][3] + b1;
            if (ACT == 1) {
                v00 = 0.5f * v00 * (1.0f + erff(v00 * 0.70710678118654752f));
                v01 = 0.5f * v01 * (1.0f + erff(v01 * 0.70710678118654752f));
                v10 = 0.5f * v10 * (1.0f + erff(v10 * 0.70710678118654752f));
                v11 = 0.5f * v11 * (1.0f + erff(v11 * 0.70710678118654752f));
            }
            if (HASRES) {
                float2 r0 = *(const float2*)(res + orow_a * N + col);
                float2 r1 = *(const float2*)(res + orow_b * N + col);
                v00 += r0.x; v01 += r0.y; v10 += r1.x; v11 += r1.y;
            }
            if (ADDPE) {
                float2 p0 = *(const float2*)(pe + (size_t)pes_a * DMODEL + col);
                float2 p1 = *(const float2*)(pe + (size_t)pes_b * DMODEL + col);
                v00 += p0.x; v01 += p0.y; v10 += p1.x; v11 += p1.y;
            }
            if (OUTBF) {
                bf16* C = (bf16*)Cout;
                __nv_bfloat162 p0 = __floats2bfloat162_rn(v00, v01);
                __nv_bfloat162 p1 = __floats2bfloat162_rn(v10, v11);
                *reinterpret_cast<uint32_t*>(C + orow_a * N + col) = *reinterpret_cast<uint32_t*>(&p0);
                *reinterpret_cast<uint32_t*>(C + orow_b * N + col) = *reinterpret_cast<uint32_t*>(&p1);
            } else {
                float* C = (float*)Cout;
                *(float2*)(C + orow_a * N + col) = make_float2(v00, v01);
                *(float2*)(C + orow_b * N + col) = make_float2(v10, v11);
            }
        }
    }
}

// ---------------- LayerNorm: 2 rows per warp, bf16 out ----------------------
__global__ void ln_kernel(const float* __restrict__ x,
                          const float* __restrict__ g,
                          const float* __restrict__ b,
                          bf16* __restrict__ y)
{
    const int warp = threadIdx.x >> 5, lane = threadIdx.x & 31;
    const int row0 = blockIdx.x * 16 + warp * 2;

    const float4* xpA = (const float4*)(x + (size_t)row0 * DMODEL);
    const float4* xpB = (const float4*)(x + (size_t)(row0 + 1) * DMODEL);
    float4 uA = xpA[lane * 2], wA = xpA[lane * 2 + 1];
    float4 uB = xpB[lane * 2], wB = xpB[lane * 2 + 1];

    float sA = uA.x + uA.y + uA.z + uA.w + wA.x + wA.y + wA.z + wA.w;
    float sB = uB.x + uB.y + uB.z + uB.w + wB.x + wB.y + wB.z + wB.w;
#pragma unroll
    for (int off = 16; off; off >>= 1) {
        sA += __shfl_xor_sync(0xffffffffu, sA, off);
        sB += __shfl_xor_sync(0xffffffffu, sB, off);
    }
    float muA = sA * (1.f / DMODEL), muB = sB * (1.f / DMODEL);

    float a0 = uA.x - muA, a1 = uA.y - muA, a2 = uA.z - muA, a3 = uA.w - muA;
    float a4 = wA.x - muA, a5 = wA.y - muA, a6 = wA.z - muA, a7 = wA.w - muA;
    float c0 = uB.x - muB, c1 = uB.y - muB, c2 = uB.z - muB, c3 = uB.w - muB;
    float c4 = wB.x - muB, c5 = wB.y - muB, c6 = wB.z - muB, c7 = wB.w - muB;
    float s2A = a0*a0 + a1*a1 + a2*a2 + a3*a3 + a4*a4 + a5*a5 + a6*a6 + a7*a7;
    float s2B = c0*c0 + c1*c1 + c2*c2 + c3*c3 + c4*c4 + c5*c5 + c6*c6 + c7*c7;
#pragma unroll
    for (int off = 16; off; off >>= 1) {
        s2A += __shfl_xor_sync(0xffffffffu, s2A, off);
        s2B += __shfl_xor_sync(0xffffffffu, s2B, off);
    }
    float invA = rsqrtf(s2A * (1.f / DMODEL) + LNEPS);
    float invB = rsqrtf(s2B * (1.f / DMODEL) + LNEPS);

    const float4* gp = (const float4*)g;
    const float4* bp = (const float4*)b;
    float4 g0 = gp[lane * 2], g1 = gp[lane * 2 + 1];
    float4 b0 = bp[lane * 2], b1 = bp[lane * 2 + 1];

    {
        __nv_bfloat162 p0 = __floats2bfloat162_rn(a0 * invA * g0.x + b0.x, a1 * invA * g0.y + b0.y);
        __nv_bfloat162 p1 = __floats2bfloat162_rn(a2 * invA * g0.z + b0.z, a3 * invA * g0.w + b0.w);
        __nv_bfloat162 p2 = __floats2bfloat162_rn(a4 * invA * g1.x + b1.x, a5 * invA * g1.y + b1.y);
        __nv_bfloat162 p3 = __floats2bfloat162_rn(a6 * invA * g1.z + b1.z, a7 * invA * g1.w + b1.w);
        uint4 o;
        o.x = *reinterpret_cast<uint32_t*>(&p0);
        o.y = *reinterpret_cast<uint32_t*>(&p1);
        o.z = *reinterpret_cast<uint32_t*>(&p2);
        o.w = *reinterpret_cast<uint32_t*>(&p3);
        *reinterpret_cast<uint4*>(y + (size_t)row0 * DMODEL + lane * 8) = o;
    }
    {
        __nv_bfloat162 p0 = __floats2bfloat162_rn(c0 * invB * g0.x + b0.x, c1 * invB * g0.y + b0.y);
        __nv_bfloat162 p1 = __floats2bfloat162_rn(c2 * invB * g0.z + b0.z, c3 * invB * g0.w + b0.w);
        __nv_bfloat162 p2 = __floats2bfloat162_rn(c4 * invB * g1.x + b1.x, c5 * invB * g1.y + b1.y);
        __nv_bfloat162 p3 = __floats2bfloat162_rn(c6 * invB * g1.z + b1.z, c7 * invB * g1.w + b1.w);
        uint4 o;
        o.x = *reinterpret_cast<uint32_t*>(&p0);
        o.y = *reinterpret_cast<uint32_t*>(&p1);
        o.z = *reinterpret_cast<uint32_t*>(&p2);
        o.w = *reinterpret_cast<uint32_t*>(&p3);
        *reinterpret_cast<uint4*>(y + (size_t)(row0 + 1) * DMODEL + lane * 8) = o;
    }
}

// ---------------- fused per-head QKV projection, full SEQ per block ----------
__global__ void qkv_kernel(const bf16* __restrict__ x1,
                           const float* __restrict__ wq, const float* __restrict__ bq,
                           const float* __restrict__ wk, const float* __restrict__ bk,
                           const float* __restrict__ wv, const float* __restrict__ bv,
                           bf16* __restrict__ q, bf16* __restrict__ k, bf16* __restrict__ v)
{
    __shared__ float wqs[32 * 33], wks[32 * 33], wvs[32 * 33];
    __shared__ float bqs[32], bks[32], bvs[32];
    __shared__ float xr[200 * 33];
    const int nh = blockIdx.x;
    const int n = nh / NHEAD, h = nh % NHEAD;
    const int t = threadIdx.x;
    const float* wqg = wq + (size_t)h * DH * DH;
    const float* wkg = wk + (size_t)h * DH * DH;
    const float* wvg = wv + (size_t)h * DH * DH;

    for (int i = t; i < DH * DH; i += 256) {
        int e = i >> 5, d = i & 31;
        wqs[e * 33 + d] = wqg[i];
        wks[e * 33 + d] = wkg[i];
        wvs[e * 33 + d] = wvg[i];
    }
    if (t < 32) { bqs[t] = bq[h * DH + t]; bks[t] = bk[h * DH + t]; bvs[t] = bv[h * DH + t]; }

    for (int i = t; i < SEQ * 32; i += 256) {
        int r = i >> 5, d = i & 31;
        xr[r * 33 + d] = __bfloat162float(x1[((size_t)n * SEQ + r) * DMODEL + h * DH + d]);
    }
    __syncthreads();

    const float scale = 0.17677669529663689f * 1.4426950408889634f;  // log2e/sqrt(32)
    const int wr = (t >> 5) * 25, lane = t & 31;
    const float bqv = bqs[lane], bkv = bks[lane], bvv = bvs[lane];
#pragma unroll 5
    for (int r = 0; r < 25; r++) {
        int s = wr + r;
        if (s >= SEQ) break;
        const float* xp = xr + s * 33;
        float aq = bqv, ak = bkv, av = bvv;
#pragma unroll
        for (int d = 0; d < 32; d++) {
            float xv = xp[d];
            aq += xv * wqs[lane * 33 + d];
            ak += xv * wks[lane * 33 + d];
            av += xv * wvs[lane * 33 + d];
        }
        size_t oidx = ((size_t)nh * SEQ + s) * DH + lane;
        q[oidx] = __float2bfloat16(aq * scale);
        k[oidx] = __float2bfloat16(ak);
        v[oidx] = __float2bfloat16(av);
    }
}

// ---------------- tensor-core flash attention per (n,h), base-2 softmax -----
// (round-15 proven config: SPAD=224, lambda body, masked last tile)
#define SPAD 224
#define NKT  7
#define KSTR 20
#define VSTR 116

__global__ void __launch_bounds__(224) attn_tc(const bf16* __restrict__ q,
                                               const bf16* __restrict__ k,
                                               const bf16* __restrict__ v,
                                               bf16* __restrict__ o)
{
    __shared__ uint32_t Ks[SPAD * KSTR];
    __shared__ uint32_t VT[32 * VSTR];

    const int nh = blockIdx.x;
    const int n = nh / NHEAD, h = nh % NHEAD;
    const int t = threadIdx.x, warp = t >> 5, lane = t & 31;
    const int g = lane >> 2, q4 = lane & 3;
    const size_t base = (size_t)nh * SEQ * DH;
    const uint32_t* q32 = (const uint32_t*)(q + base);
    const uint32_t* k32 = (const uint32_t*)(k + base);
    const uint32_t* v32 = (const uint32_t*)(v + base);

    for (int i = t; i < SPAD * 16; i += 224) {
        int r = i >> 4, c = i & 15;
        Ks[r * KSTR + c] = (r < SEQ) ? k32[r * 16 + c] : 0u;
    }
    bf16* VT16 = (bf16*)VT;
    for (int i = t; i < SPAD * 16; i += 224) {
        int tt = i >> 4, c = i & 15;
        uint32_t val = (tt < SEQ) ? v32[tt * 16 + c] : 0u;
        __nv_bfloat162 pr = *reinterpret_cast<__nv_bfloat162*>(&val);
        VT16[(2 * c)     * (VSTR * 2) + tt] = pr.x;
        VT16[(2 * c + 1) * (VSTR * 2) + tt] = pr.y;
    }
    __syncthreads();

    const int qbase = warp * 32;
    uint32_t qf[2][2][4];
#pragma unroll
    for (int mi = 0; mi < 2; mi++) {
        int r0 = qbase + mi * 16 + g, r1 = r0 + 8;
        bool v0 = r0 < SEQ, v1 = r1 < SEQ;
#pragma unroll
        for (int ks = 0; ks < 2; ks++) {
            qf[mi][ks][0] = v0 ? q32[r0 * 16 + ks * 8 + q4]     : 0u;
            qf[mi][ks][1] = v1 ? q32[r1 * 16 + ks * 8 + q4]     : 0u;
            qf[mi][ks][2] = v0 ? q32[r0 * 16 + ks * 8 + q4 + 4] : 0u;
            qf[mi][ks][3] = v1 ? q32[r1 * 16 + ks * 8 + q4 + 4] : 0u;
        }
    }

    float Oa[2][4][4];
#pragma unroll
    for (int mi = 0; mi < 2; mi++)
#pragma unroll
        for (int ne = 0; ne < 4; ne++)
#pragma unroll
            for (int e = 0; e < 4; e++) Oa[mi][ne][e] = 0.f;
    float m_[2][2] = {{-1e30f, -1e30f}, {-1e30f, -1e30f}};
    float l_[2][2] = {{0.f, 0.f}, {0.f, 0.f}};

    auto body = [&](int kt, bool last_mask) {
        float sc[2][4][4];
#pragma unroll
        for (int mi = 0; mi < 2; mi++)
#pragma unroll
            for (int ni = 0; ni < 4; ni++)
#pragma unroll
                for (int e = 0; e < 4; e++) sc[mi][ni][e] = 0.f;

        uint32_t kf[2][4][2];
#pragma unroll
        for (int ks = 0; ks < 2; ks++)
#pragma unroll
            for (int ni = 0; ni < 4; ni++) {
                int r = kt * 32 + ni * 8 + g;
                kf[ks][ni][0] = Ks[r * KSTR + ks * 8 + q4];
                kf[ks][ni][1] = Ks[r * KSTR + ks * 8 + q4 + 4];
            }
#pragma unroll
        for (int mi = 0; mi < 2; mi++)
#pragma unroll
            for (int ni = 0; ni < 4; ni++)
#pragma unroll
                for (int ks = 0; ks < 2; ks++)
                    mma_bf16(sc[mi][ni], qf[mi][ks], kf[ks][ni]);

        if (last_mask) {
#pragma unroll
            for (int mi = 0; mi < 2; mi++)
#pragma unroll
                for (int ni = 0; ni < 4; ni++) {
                    int col = kt * 32 + ni * 8 + q4 * 2;
#pragma unroll
                    for (int hf = 0; hf < 2; hf++) {
                        if (col     >= SEQ) sc[mi][ni][hf * 2]     = -1e30f;
                        if (col + 1 >= SEQ) sc[mi][ni][hf * 2 + 1] = -1e30f;
                    }
                }
        }

#pragma unroll
        for (int mi = 0; mi < 2; mi++) {
#pragma unroll
            for (int hf = 0; hf < 2; hf++) {
                float mx = fmaxf(fmaxf(sc[mi][0][hf * 2], sc[mi][0][hf * 2 + 1]),
                                 fmaxf(sc[mi][1][hf * 2], sc[mi][1][hf * 2 + 1]));
                mx = fmaxf(mx, fmaxf(fmaxf(sc[mi][2][hf * 2], sc[mi][2][hf * 2 + 1]),
                                     fmaxf(sc[mi][3][hf * 2], sc[mi][3][hf * 2 + 1])));
                mx = fmaxf(mx, __shfl_xor_sync(0xffffffffu, mx, 1));
                mx = fmaxf(mx, __shfl_xor_sync(0xffffffffu, mx, 2));
                float mnew = fmaxf(m_[mi][hf], mx);
                float f = ex2f(m_[mi][hf] - mnew);
                m_[mi][hf] = mnew;
                float rs = 0.f;
#pragma unroll
                for (int ni = 0; ni < 4; ni++) {
                    float p0 = ex2f(sc[mi][ni][hf * 2]     - mnew);
                    float p1 = ex2f(sc[mi][ni][hf * 2 + 1] - mnew);
                    sc[mi][ni][hf * 2]     = p0;
                    sc[mi][ni][hf * 2 + 1] = p1;
                    rs += p0 + p1;
                }
                rs += __shfl_xor_sync(0xffffffffu, rs, 1);
                rs += __shfl_xor_sync(0xffffffffu, rs, 2);
                l_[mi][hf] = l_[mi][hf] * f + rs;
#pragma unroll
                for (int ne = 0; ne < 4; ne++) {
                    Oa[mi][ne][hf * 2]     *= f;
                    Oa[mi][ne][hf * 2 + 1] *= f;
                }
            }
        }

        uint32_t pa[2][2][4];
#pragma unroll
        for (int mi = 0; mi < 2; mi++)
#pragma unroll
            for (int ks = 0; ks < 2; ks++) {
                __nv_bfloat162 t0 = __floats2bfloat162_rn(sc[mi][2 * ks][0],     sc[mi][2 * ks][1]);
                __nv_bfloat162 t1 = __floats2bfloat162_rn(sc[mi][2 * ks][2],     sc[mi][2 * ks][3]);
                __nv_bfloat162 t2 = __floats2bfloat162_rn(sc[mi][2 * ks + 1][0], sc[mi][2 * ks + 1][1]);
                __nv_bfloat162 t3 = __floats2bfloat162_rn(sc[mi][2 * ks + 1][2], sc[mi][2 * ks + 1][3]);
                pa[mi][ks][0] = *reinterpret_cast<uint32_t*>(&t0);
                pa[mi][ks][1] = *reinterpret_cast<uint32_t*>(&t1);
                pa[mi][ks][2] = *reinterpret_cast<uint32_t*>(&t2);
                pa[mi][ks][3] = *reinterpret_cast<uint32_t*>(&t3);
            }

        uint32_t vf[2][4][2];
#pragma unroll
        for (int ks = 0; ks < 2; ks++)
#pragma unroll
            for (int ne = 0; ne < 4; ne++) {
                int r = ne * 8 + g;
                int cu = kt * 16 + ks * 8 + q4;
                vf[ks][ne][0] = VT[r * VSTR + cu];
                vf[ks][ne][1] = VT[r * VSTR + cu + 4];
            }
#pragma unroll
        for (int mi = 0; mi < 2; mi++)
#pragma unroll
            for (int ne = 0; ne < 4; ne++)
#pragma unroll
                for (int ks = 0; ks < 2; ks++)
                    mma_bf16(Oa[mi][ne], pa[mi][ks], vf[ks][ne]);
    };

    for (int kt = 0; kt < NKT - 1; kt++) body(kt, false);
    body(NKT - 1, true);

#pragma unroll
    for (int mi = 0; mi < 2; mi++) {
#pragma unroll
        for (int hf = 0; hf < 2; hf++) {
            int row = qbase + mi * 16 + hf * 8 + g;
            if (row >= SEQ) continue;
            float inv = 1.f / l_[mi][hf];
            bf16* op = o + ((size_t)n * SEQ + row) * DMODEL + h * DH;
#pragma unroll
            for (int ne = 0; ne < 4; ne++) {
                __nv_bfloat162 p = __floats2bfloat162_rn(Oa[mi][ne][hf * 2] * inv,
                                                         Oa[mi][ne][hf * 2 + 1] * inv);
                *reinterpret_cast<uint32_t*>(op + ne * 8 + q4 * 2) = *reinterpret_cast<uint32_t*>(&p);
            }
        }
    }
}

// ---------------- softmax over precomputed logits ---------------------------
__global__ void softmax_head_kernel(const float* __restrict__ logits_in,
                                    float* __restrict__ out)
{
    __shared__ float logits[OUTC];
    __shared__ float red[8];
    const int n = blockIdx.x;
    const int t = threadIdx.x, wid = t >> 5, lane = t & 31;

    for (int j = t; j < OUTC; j += 256) logits[j] = logits_in[(size_t)n * OUTP + j];
    __syncthreads();

    float mx = -1e30f;
    for (int j = t; j < OUTC; j += 256) mx = fmaxf(mx, logits[j]);
#pragma unroll
    for (int off = 16; off; off >>= 1) mx = fmaxf(mx, __shfl_xor_sync(0xffffffffu, mx, off));
    if (lane == 0) red[wid] = mx;
    __syncthreads();
    float bm = -1e30f;
#pragma unroll
    for (int i = 0; i < 8; i++) bm = fmaxf(bm, red[i]);
    __syncthreads();

    float sum = 0.f;
    for (int j = t; j < OUTC; j += 256) {
        float e = __expf(logits[j] - bm);
        logits[j] = e;
        sum += e;
    }
#pragma unroll
    for (int off = 16; off; off >>= 1) sum += __shfl_xor_sync(0xffffffffu, sum, off);
    if (lane == 0) red[wid] = sum;
    __syncthreads();
    float bs = 0.f;
#pragma unroll
    for (int i = 0; i < 8; i++) bs += red[i];
    float inv = 1.f / bs;
    __syncthreads();
    for (int j = t; j < OUTC; j += 256) out[(size_t)n * OUTC + j] = logits[j] * inv;
}

// ---------------- launcher ----------------
extern "C" void kernel_launch(void* const* d_in, const int* in_sizes, int n_in,
                              void* d_out, int out_size)
{
    const float* images  = (const float*)d_in[0];
    const float* w_map   = (const float*)d_in[1];
    const float* b_map   = (const float*)d_in[2];
    const float* cls_tok = (const float*)d_in[3];
    const float* norm1_g = (const float*)d_in[4];
    const float* norm1_b = (const float*)d_in[5];
    const float* wq      = (const float*)d_in[6];
    const float* bq      = (const float*)d_in[7];
    const float* wk      = (const float*)d_in[8];
    const float* bk      = (const float*)d_in[9];
    const float* wv      = (const float*)d_in[10];
    const float* bv      = (const float*)d_in[11];
    const float* w_last  = (const float*)d_in[12];
    const float* b_last  = (const float*)d_in[13];
    const float* norm2_g = (const float*)d_in[14];
    const float* norm2_b = (const float*)d_in[15];
    const float* w_mlp1  = (const float*)d_in[16];
    const float* b_mlp1  = (const float*)d_in[17];
    const float* w_mlp2  = (const float*)d_in[18];
    const float* b_mlp2  = (const float*)d_in[19];
    const float* w_out   = (const float*)d_in[20];
    const float* b_out   = (const float*)d_in[21];
    float* out = (float*)d_out;

    bf16 *patches, *x1b, *qb, *kb, *vb, *ob, *h1b;
    bf16 *wmapb, *wlastb, *wmlp1b, *wmlp2b, *wcat, *ccat;
    float *X, *pe, *bout_pad, *logits;
    cudaGetSymbolAddress((void**)&patches, g_patches_b);
    cudaGetSymbolAddress((void**)&X,   g_X);
    cudaGetSymbolAddress((void**)&x1b, g_x1b);
    cudaGetSymbolAddress((void**)&qb,  g_qb);
    cudaGetSymbolAddress((void**)&kb,  g_kb);
    cudaGetSymbolAddress((void**)&vb,  g_vb);
    cudaGetSymbolAddress((void**)&ob,  g_ob);
    cudaGetSymbolAddress((void**)&h1b, g_h1b);
    cudaGetSymbolAddress((void**)&pe,  g_pe);
    cudaGetSymbolAddress((void**)&wmapb,  g_wmapb);
    cudaGetSymbolAddress((void**)&wlastb, g_wlastb);
    cudaGetSymbolAddress((void**)&wmlp1b, g_wmlp1b);
    cudaGetSymbolAddress((void**)&wmlp2b, g_wmlp2b);
    cudaGetSymbolAddress((void**)&wcat, g_wout_cat);
    cudaGetSymbolAddress((void**)&ccat, g_cls_cat);
    cudaGetSymbolAddress((void**)&bout_pad, g_bout_pad);
    cudaGetSymbolAddress((void**)&logits,   g_logits);

    cudaFuncSetAttribute(gemm_bf<0, false, false, true >, cudaFuncAttributeMaxDynamicSharedMemorySize, GEMM_SMEM);
    cudaFuncSetAttribute(gemm_bf<0, true,  false, false>, cudaFuncAttributeMaxDynamicSharedMemorySize, GEMM_SMEM);
    cudaFuncSetAttribute(gemm_bf<1, false, true,  false>, cudaFuncAttributeMaxDynamicSharedMemorySize, GEMM_SMEM);
    cudaFuncSetAttribute(gemm_bf<0, false, false, false>, cudaFuncAttributeMaxDynamicSharedMemorySize, GEMM_SMEM);

    // 0) weight conversion to bf16 (+ concatenated head weights)
    {
        int n0 = DMODEL * IN_D;
        int n1 = NLAYER * DMODEL * DMODEL;
        int n3 = NLAYER * 4 * DMODEL * DMODEL;
        int totf4 = (n0 + n1 + 2 * n3) / 4;
        cvt_all_kernel<<<(totf4 + 255) / 256, 256>>>(
            w_map, wmapb, n0, w_last, wlastb, n1,
            w_mlp1, wmlp1b, n3, w_mlp2, wmlp2b, n3);
        int hw = OUTP * DMODEL / 4;
        cvt_head_kernel<<<(hw + 255) / 256, 256>>>(w_out, b_out, wcat, bout_pad);
    }

    // 1) patches + PE table
    {
        int tot = BATCH * NP * IN_D / 8;
        patch_kernel<<<(tot + 255) / 256, 256>>>(images, patches);
        int pt = SEQ * DMODEL;
        pe_kernel<<<(pt + 255) / 256, 256>>>(pe);
    }

    // 2) patch-embed GEMM fused with assemble
    gemm_bf<0, false, false, true><<<dim3(DMODEL / 128, (BATCH * NP) / 128), 256, GEMM_SMEM>>>(
        patches, wmapb, b_map, nullptr, pe, X, BATCH * NP, DMODEL, IN_D);

    // 2b) cls rows
    cls_kernel<<<(BATCH * DMODEL + 255) / 256, 256>>>(cls_tok, pe, X);

    const int MROWS = BATCH * SEQ;   // 25216 = 16*1576

    for (int l = 0; l < NLAYER; l++) {
        ln_kernel<<<MROWS / 16, 256>>>(X, norm1_g + l * DMODEL, norm1_b + l * DMODEL, x1b);

        qkv_kernel<<<BATCH * NHEAD, 256>>>(
            x1b,
            wq + (size_t)l * NHEAD * DH * DH, bq + (size_t)l * NHEAD * DH,
            wk + (size_t)l * NHEAD * DH * DH, bk + (size_t)l * NHEAD * DH,
            wv + (size_t)l * NHEAD * DH * DH, bv + (size_t)l * NHEAD * DH,
            qb, kb, vb);

        attn_tc<<<BATCH * NHEAD, 224>>>(qb, kb, vb, ob);

        gemm_bf<0, true, false, false><<<dim3(DMODEL / 128, MROWS / 128), 256, GEMM_SMEM>>>(
            ob, wlastb + (size_t)l * DMODEL * DMODEL, b_last + l * DMODEL, X, nullptr, X,
            MROWS, DMODEL, DMODEL);

        ln_kernel<<<MROWS / 16, 256>>>(X, norm2_g + l * DMODEL, norm2_b + l * DMODEL, x1b);

        gemm_bf<1, false, true, false><<<dim3((4 * DMODEL) / 128, MROWS / 128), 256, GEMM_SMEM>>>(
            x1b, wmlp1b + (size_t)l * 4 * DMODEL * DMODEL, b_mlp1 + l * 4 * DMODEL,
            nullptr, nullptr, h1b, MROWS, 4 * DMODEL, DMODEL);

        gemm_bf<0, true, false, false><<<dim3(DMODEL / 128, MROWS / 128), 256, GEMM_SMEM>>>(
            h1b, wmlp2b + (size_t)l * 4 * DMODEL * DMODEL, b_mlp2 + l * DMODEL, X, nullptr, X,
            MROWS, DMODEL, 4 * DMODEL);
    }

    // head: cls concat extraction -> single compensated bf16 GEMM (K=768) -> softmax
    cls_extract_kernel<<<(BATCH * DMODEL / 4 + 255) / 256, 256>>>(X, ccat);
    gemm_bf<0, false, false, false><<<dim3(OUTP / 128, BATCH / 128), 256, GEMM_SMEM>>>(
        ccat, wcat, bout_pad, nullptr, nullptr, logits, BATCH, OUTP, HKDIM);
    softmax_head_kernel<<<BATCH, 256>>>(logits, out);
}